// round 14
// baseline (speedup 1.0000x reference)
#include <cuda_runtime.h>
#include <cuda_fp16.h>
#include <math.h>
#include <stdint.h>

// Problem constants
#define NTOK   32768
#define DIM    512
#define NOPS   8

// GEMM tiling: single-pass fp16, BK=64 halfs = 128B/row (SW128 atom)
#define BM 128
#define BN 128
#define BK 64
#define NCHUNK (DIM / BK)      // 8
#define NITER NCHUNK           // single pass
#define MAX_TILES 264
#define PERM_SIZE (MAX_TILES * BM)

// SMEM: 3 stages x (A 16KB + B 16KB)
#define STAGE_BYTES 32768
#define B_OFF 16384
#define NSTAGE 3
#define SMEM_DYN (NSTAGE * STAGE_BYTES + 1024)

#define SW128(o) ((o) ^ (((o) >> 3) & 0x70))

// ---------------- device scratch ----------------
__device__ int g_route[NTOK];
__device__ int g_cursor[NOPS];
__device__ int g_base[NOPS];
__device__ int g_cnt[NOPS];
__device__ int g_perm[PERM_SIZE];
__device__ int g_tile_op[MAX_TILES];
__device__ int g_tile_row[MAX_TILES];
__device__ int g_ntiles;

__device__ __half g_Wh[NOPS * DIM * DIM];           // fp16 W
__device__ __half g_Ah[(size_t)PERM_SIZE * DIM];    // fp16 permuted x

// ---------------- PTX helpers ----------------
__device__ __forceinline__ uint32_t smem_u32(const void* p) {
    uint32_t a;
    asm("{ .reg .u64 t; cvta.to.shared.u64 t, %1; cvt.u32.u64 %0, t; }" : "=r"(a) : "l"(p));
    return a;
}
__device__ __forceinline__ void cp_async16(uint32_t dst, const void* src) {
    asm volatile("cp.async.cg.shared.global [%0], [%1], 16;" :: "r"(dst), "l"(src) : "memory");
}
__device__ __forceinline__ void cp_commit() {
    asm volatile("cp.async.commit_group;" ::: "memory");
}
template <int N>
__device__ __forceinline__ void cp_wait() {
    asm volatile("cp.async.wait_group %0;" :: "n"(N) : "memory");
}
__device__ __forceinline__ void ldsm_x4(uint32_t& r0, uint32_t& r1, uint32_t& r2, uint32_t& r3,
                                        uint32_t addr) {
    asm volatile("ldmatrix.sync.aligned.m8n8.x4.shared.b16 {%0,%1,%2,%3}, [%4];"
                 : "=r"(r0), "=r"(r1), "=r"(r2), "=r"(r3) : "r"(addr));
}
__device__ __forceinline__ void mma_f16(float* c, const uint32_t* a, const uint32_t* b) {
    asm volatile(
        "mma.sync.aligned.m16n8k16.row.col.f32.f16.f16.f32 "
        "{%0,%1,%2,%3}, {%4,%5,%6,%7}, {%8,%9}, {%0,%1,%2,%3};"
        : "+f"(c[0]), "+f"(c[1]), "+f"(c[2]), "+f"(c[3])
        : "r"(a[0]), "r"(a[1]), "r"(a[2]), "r"(a[3]), "r"(b[0]), "r"(b[1]));
}
__device__ __forceinline__ uint32_t pack_h2(float a, float b) {
    __half2 h = __floats2half2_rn(a, b);
    return *(uint32_t*)&h;
}

// ---------------- aux kernels ----------------

// W -> fp16 + routing decision
__global__ void wsplit_route_kernel(const float* __restrict__ W,
                                    const float* __restrict__ logits,
                                    const float* __restrict__ gumbel) {
    int i = blockIdx.x * blockDim.x + threadIdx.x;    // 0 .. 524287
    float4 w = ((const float4*)W)[i];
    uint2 hw;
    hw.x = pack_h2(w.x, w.y);
    hw.y = pack_h2(w.z, w.w);
    *(uint2*)&g_Wh[(size_t)i * 4] = hw;

    if (i < NTOK) {
        float best = -INFINITY;
        int bi = 0;
#pragma unroll
        for (int k = 0; k < NOPS; k++) {
            float v = logits[i * NOPS + k] + gumbel[i * NOPS + k];
            if (v > best) { best = v; bi = k; }
        }
        g_route[i] = bi;
    }
}

__global__ void scan_kernel() {
    __shared__ int cnt[NOPS * 8];
    __shared__ int s_base[NOPS], s_tb[NOPS + 1], s_cnt[NOPS];
    const int tid = threadIdx.x;
    if (tid < NOPS * 8) cnt[tid] = 0;
    __syncthreads();
    const int rep = (tid & 7) * NOPS;
    for (int t = tid; t < NTOK; t += 256)
        atomicAdd(&cnt[rep + g_route[t]], 1);
    __syncthreads();
    if (tid == 0) {
        int off = 0, tl = 0;
        for (int g = 0; g < NOPS; g++) {
            int c = 0;
            for (int rs = 0; rs < 8; rs++) c += cnt[rs * NOPS + g];
            s_cnt[g] = c; g_cnt[g] = c;
            s_base[g] = off; g_base[g] = off;
            g_cursor[g] = 0;
            s_tb[g] = tl;
            int nt = (c + BM - 1) / BM;
            tl += nt; off += nt * BM;
        }
        s_tb[NOPS] = tl;
        g_ntiles = tl;
    }
    __syncthreads();
    const int ntl = s_tb[NOPS];
    for (int tile = tid; tile < ntl; tile += 256) {
        int g = 0;
        while (tile >= s_tb[g + 1]) g++;
        g_tile_op[tile] = g;
        g_tile_row[tile] = s_base[g] + (tile - s_tb[g]) * BM;
    }
    for (int g = 0; g < NOPS; g++) {
        int c = s_cnt[g];
        int start = s_base[g] + c;
        int end   = s_base[g] + ((c + BM - 1) / BM) * BM;
        for (int p = start + tid; p < end; p += 256) g_perm[p] = -1;
    }
}

// merged scatter + A fp16-convert: one warp per token; extra warps zero padding rows
#define PAD_WARPS 1024
__global__ void scatter_convert_kernel(const float* __restrict__ x) {
    const int w    = (blockIdx.x * blockDim.x + threadIdx.x) >> 5;
    const int lane = threadIdx.x & 31;

    if (w < NTOK) {
        const int t = w;
        int row = 0;
        if (lane == 0) {
            int op  = g_route[t];
            int pos = atomicAdd(&g_cursor[op], 1);
            row = g_base[op] + pos;
            g_perm[row] = t;
        }
        row = __shfl_sync(0xffffffffu, row, 0);
        const float4* src = (const float4*)(x + (size_t)t * DIM);
        __half* dst = g_Ah + (size_t)row * DIM;
#pragma unroll
        for (int j = 0; j < 4; j++) {
            const int c4 = j * 32 + lane;
            float4 v = src[c4];
            uint2 hw;
            hw.x = pack_h2(v.x, v.y);
            hw.y = pack_h2(v.z, v.w);
            *(uint2*)(dst + c4 * 4) = hw;
        }
    } else {
        const int p = w - NTOK;
        if (p >= PAD_WARPS) return;
        const int g = p >> 7, j = p & 127;
        const int cnt  = g_cnt[g];
        const int base = g_base[g];
        const int row  = base + cnt + j;
        const int end  = base + ((cnt + BM - 1) / BM) * BM;
        if (row < end) {
            uint2 z = make_uint2(0u, 0u);
            __half* dst = g_Ah + (size_t)row * DIM;
#pragma unroll
            for (int q = 0; q < 4; q++)
                *(uint2*)(dst + (q * 32 + lane) * 4) = z;
        }
    }
}

__device__ __forceinline__ float apply_act(int op, float h) {
    switch (op) {
        case 0:  return 0.5f * h * (1.0f + erff(h * 0.7071067811865476f));
        case 1:  return fmaxf(h, 0.0f);
        case 2:  { float r = fmaxf(h, 0.0f); return r * r; }
        case 3:  return h / (1.0f + expf(-h));
        case 4:  return tanhf(h);
        case 5:  return 1.0f / (1.0f + expf(-h));
        case 6:  return h;
        default: return -h;
    }
}

// ---------------- fp16 MMA grouped GEMM: mi-pipelined inner loop ----------------
// 256 threads = 8 warps (2 M x 4 N), warp tile 64x32, BK=64 halfs = 128B/row.
// Per kk: load B frags, then ping-pong A frags across mi so each LDSM hides
// under the previous mi's MMAs (keeps live fragment regs at 16 instead of 24).
__global__ __launch_bounds__(256)
void gemm_kernel(float* __restrict__ out) {
    extern __shared__ char dsm[];
    const int bx = blockIdx.x;
    if (bx >= g_ntiles) return;

    const int op   = g_tile_op[bx];
    const int row0 = g_tile_row[bx];
    const int n0   = blockIdx.y * BN;
    const int tid  = threadIdx.x;
    const int wid  = tid >> 5;
    const int lid  = tid & 31;
    const int wm   = wid >> 2;     // 0..1
    const int wn   = wid & 3;      // 0..3

    char* sbase = (char*)(((uintptr_t)dsm + 1023) & ~(uintptr_t)1023);
    const uint32_t sb = smem_u32(sbase);

    const __half* __restrict__ Ag0 = g_Ah + (size_t)row0 * DIM;
    const __half* __restrict__ Bg0 = g_Wh + (size_t)op * DIM * DIM + (size_t)n0 * DIM;

    // store mapping: 1024 16B units per stage half; r = sid>>3 (row), ks = sid&7
    const int lr = tid >> 3;
    const int ks = tid & 7;
    const uint32_t sw_col = (uint32_t)(ks * 16);

    // ldmatrix addressing (identical to validated path: 128B rows, SW128)
    const int a_row = wm * 64 + (lid & 15);
    const uint32_t a_rowoff = (uint32_t)(a_row * 128);
    const uint32_t a_mask = (uint32_t)((a_row & 7) << 4);
    const uint32_t a_col0 = (uint32_t)((lid >> 4) << 4);
    const int b_row = wn * 32 + (lid & 7) + ((lid >> 4) << 3);
    const uint32_t b_rowoff = (uint32_t)(B_OFF + b_row * 128);
    const uint32_t b_mask = (uint32_t)((b_row & 7) << 4);
    const uint32_t b_col0 = (uint32_t)(((lid >> 3) & 1) << 4);

    float acc[4][4][4];
#pragma unroll
    for (int i = 0; i < 4; i++)
#pragma unroll
        for (int j = 0; j < 4; j++)
#pragma unroll
            for (int q = 0; q < 4; q++) acc[i][j][q] = 0.0f;

    auto load_chunk = [&](int kc, int s) {
        const __half* Ag = Ag0 + kc * BK;
        const __half* Bg = Bg0 + kc * BK;
        const uint32_t As = sb + s * STAGE_BYTES;
        const uint32_t Bs = As + B_OFF;
#pragma unroll
        for (int j = 0; j < 4; j++) {
            int r = lr + j * 32;
            uint32_t soff = SW128((uint32_t)(r * 128) + sw_col);
            cp_async16(As + soff, Ag + (size_t)r * DIM + ks * 8);
            cp_async16(Bs + soff, Bg + (size_t)r * DIM + ks * 8);
        }
        cp_commit();
    };

    load_chunk(0, 0);
    load_chunk(1, 1);

    int s = 0;
    for (int i = 0; i < NITER; i++) {
        cp_wait<1>();
        __syncthreads();
        // stage (i+2)%3 was last read at iteration i-1 -> safe to overwrite now
        if (i + 2 < NITER) {
            int s2 = s + 2; if (s2 >= NSTAGE) s2 -= NSTAGE;
            load_chunk(i + 2, s2);
        } else {
            cp_commit();   // keep group count consistent for cp_wait<1>
        }

        const uint32_t stg = sb + s * STAGE_BYTES;
        const uint32_t As_base = stg + a_rowoff;
        const uint32_t Bs_base = stg + b_rowoff;

#pragma unroll
        for (int kk = 0; kk < 4; kk++) {               // 4 x k16 per chunk
            const uint32_t a_col = (a_col0 + kk * 32) ^ a_mask;
            const uint32_t b_col = (b_col0 + kk * 32) ^ b_mask;

            uint32_t b[4][2];
#pragma unroll
            for (int nb = 0; nb < 2; nb++)
                ldsm_x4(b[nb * 2][0], b[nb * 2][1], b[nb * 2 + 1][0], b[nb * 2 + 1][1],
                        Bs_base + nb * (16 * 128) + b_col);

            // mi-pipelined A: prefetch mi+1's fragments before mi's MMAs
            uint32_t a_cur[4], a_nxt[4];
            ldsm_x4(a_cur[0], a_cur[1], a_cur[2], a_cur[3], As_base + a_col);
#pragma unroll
            for (int mi = 0; mi < 4; mi++) {
                if (mi < 3)
                    ldsm_x4(a_nxt[0], a_nxt[1], a_nxt[2], a_nxt[3],
                            As_base + (mi + 1) * (16 * 128) + a_col);
#pragma unroll
                for (int ni = 0; ni < 4; ni++)
                    mma_f16(acc[mi][ni], a_cur, b[ni]);
#pragma unroll
                for (int q = 0; q < 4; q++) a_cur[q] = a_nxt[q];
            }
        }

        if (++s >= NSTAGE) s -= NSTAGE;
    }

    // epilogue: activation + scatter to original token rows
    const int r = lid >> 2;
    const int c = (lid & 3) * 2;
#pragma unroll
    for (int mi = 0; mi < 4; mi++) {
        const int m_lo = wm * 64 + mi * 16 + r;
        const int tok_lo = g_perm[row0 + m_lo];
        const int tok_hi = g_perm[row0 + m_lo + 8];
        float* o_lo = (tok_lo >= 0) ? (out + (size_t)tok_lo * DIM + n0) : nullptr;
        float* o_hi = (tok_hi >= 0) ? (out + (size_t)tok_hi * DIM + n0) : nullptr;
#pragma unroll
        for (int ni = 0; ni < 4; ni++) {
            const int n = wn * 32 + ni * 8 + c;
            if (o_lo) {
                float2 v;
                v.x = apply_act(op, acc[mi][ni][0]);
                v.y = apply_act(op, acc[mi][ni][1]);
                *(float2*)(o_lo + n) = v;
            }
            if (o_hi) {
                float2 v;
                v.x = apply_act(op, acc[mi][ni][2]);
                v.y = apply_act(op, acc[mi][ni][3]);
                *(float2*)(o_hi + n) = v;
            }
        }
    }
}

// ---------------- launch ----------------
extern "C" void kernel_launch(void* const* d_in, const int* in_sizes, int n_in,
                              void* d_out, int out_size) {
    const float* x      = (const float*)d_in[0];
    const float* logits = (const float*)d_in[1];
    const float* gumbel = (const float*)d_in[2];
    const float* W      = (const float*)d_in[3];
    float* out          = (float*)d_out;

    cudaFuncSetAttribute(gemm_kernel, cudaFuncAttributeMaxDynamicSharedMemorySize, SMEM_DYN);

    wsplit_route_kernel<<<(NOPS * DIM * DIM / 4 + 255) / 256, 256>>>(W, logits, gumbel);
    scan_kernel<<<1, 256>>>();
    scatter_convert_kernel<<<((NTOK + PAD_WARPS) * 32) / 256, 256>>>(x);

    dim3 grid(MAX_TILES, DIM / BN);
    gemm_kernel<<<grid, 256, SMEM_DYN>>>(out);
}

// round 16
// speedup vs baseline: 1.0495x; 1.0495x over previous
#include <cuda_runtime.h>
#include <cuda_fp16.h>
#include <math.h>
#include <stdint.h>

// Problem constants
#define NTOK   32768
#define DIM    512
#define NOPS   8

// GEMM tiling: single-pass fp16, BK=64 halfs = 128B/row (SW128 atom)
#define BM 128
#define BN 128
#define BK 64
#define NCHUNK (DIM / BK)      // 8
#define NITER NCHUNK
#define MAX_TILES 264
#define PERM_SIZE (MAX_TILES * BM)

// SMEM: 3 stages x (A 16KB + B 16KB)
#define STAGE_BYTES 32768
#define B_OFF 16384
#define NSTAGE 3
#define SMEM_DYN (NSTAGE * STAGE_BYTES + 1024)

#define SW128(o) ((o) ^ (((o) >> 3) & 0x70))

// ---------------- device scratch ----------------
__device__ int g_route[NTOK];
__device__ int g_cursor[NOPS];
__device__ int g_base[NOPS];
__device__ int g_perm[PERM_SIZE];
__device__ int g_tile_op[MAX_TILES];
__device__ int g_tile_row[MAX_TILES];
__device__ int g_ntiles;

__device__ __half g_Wh[NOPS * DIM * DIM];        // fp16 W
__device__ __half g_Xh[(size_t)NTOK * DIM];      // fp16 x, ORIGINAL token order

// ---------------- PTX helpers ----------------
__device__ __forceinline__ uint32_t smem_u32(const void* p) {
    uint32_t a;
    asm("{ .reg .u64 t; cvta.to.shared.u64 t, %1; cvt.u32.u64 %0, t; }" : "=r"(a) : "l"(p));
    return a;
}
__device__ __forceinline__ void cp_async16(uint32_t dst, const void* src) {
    asm volatile("cp.async.cg.shared.global [%0], [%1], 16;" :: "r"(dst), "l"(src) : "memory");
}
// zero-fill variant: copies src_size bytes, zero-fills the rest of the 16
__device__ __forceinline__ void cp_async16z(uint32_t dst, const void* src, uint32_t src_size) {
    asm volatile("cp.async.cg.shared.global [%0], [%1], 16, %2;"
                 :: "r"(dst), "l"(src), "r"(src_size) : "memory");
}
__device__ __forceinline__ void cp_commit() {
    asm volatile("cp.async.commit_group;" ::: "memory");
}
template <int N>
__device__ __forceinline__ void cp_wait() {
    asm volatile("cp.async.wait_group %0;" :: "n"(N) : "memory");
}
__device__ __forceinline__ void ldsm_x4(uint32_t& r0, uint32_t& r1, uint32_t& r2, uint32_t& r3,
                                        uint32_t addr) {
    asm volatile("ldmatrix.sync.aligned.m8n8.x4.shared.b16 {%0,%1,%2,%3}, [%4];"
                 : "=r"(r0), "=r"(r1), "=r"(r2), "=r"(r3) : "r"(addr));
}
__device__ __forceinline__ void mma_f16(float* c, const uint32_t* a, const uint32_t* b) {
    asm volatile(
        "mma.sync.aligned.m16n8k16.row.col.f32.f16.f16.f32 "
        "{%0,%1,%2,%3}, {%4,%5,%6,%7}, {%8,%9}, {%0,%1,%2,%3};"
        : "+f"(c[0]), "+f"(c[1]), "+f"(c[2]), "+f"(c[3])
        : "r"(a[0]), "r"(a[1]), "r"(a[2]), "r"(a[3]), "r"(b[0]), "r"(b[1]));
}
__device__ __forceinline__ uint32_t pack_h2(float a, float b) {
    __half2 h = __floats2half2_rn(a, b);
    return *(uint32_t*)&h;
}

// ---------------- aux kernels ----------------

// launch 1: x -> fp16 (original order) + W -> fp16 + routing decision
#define X_F4 ((size_t)NTOK * DIM / 4)        // 4,194,304 float4
#define W_F4 (NOPS * DIM * DIM / 4)          // 524,288 float4
__global__ void prep_kernel(const float* __restrict__ x,
                            const float* __restrict__ W,
                            const float* __restrict__ logits,
                            const float* __restrict__ gumbel) {
    size_t i = (size_t)blockIdx.x * blockDim.x + threadIdx.x;   // 0 .. X_F4-1
    float4 v = ((const float4*)x)[i];
    uint2 hv;
    hv.x = pack_h2(v.x, v.y);
    hv.y = pack_h2(v.z, v.w);
    *(uint2*)&g_Xh[i * 4] = hv;

    if (i < W_F4) {
        float4 w = ((const float4*)W)[i];
        uint2 hw;
        hw.x = pack_h2(w.x, w.y);
        hw.y = pack_h2(w.z, w.w);
        *(uint2*)&g_Wh[i * 4] = hw;
    }
    if (i < NTOK) {
        float best = -INFINITY;
        int bi = 0;
#pragma unroll
        for (int k = 0; k < NOPS; k++) {
            float vv = logits[i * NOPS + k] + gumbel[i * NOPS + k];
            if (vv > best) { best = vv; bi = k; }
        }
        g_route[i] = bi;
    }
}

// launch 2: count routes, build bases + tile metadata, zero cursors, mark padding perm
__global__ void scan_kernel() {
    __shared__ int cnt[NOPS * 8];
    __shared__ int s_base[NOPS], s_tb[NOPS + 1], s_cnt[NOPS];
    const int tid = threadIdx.x;
    if (tid < NOPS * 8) cnt[tid] = 0;
    __syncthreads();
    const int rep = (tid & 7) * NOPS;
    for (int t = tid; t < NTOK; t += 256)
        atomicAdd(&cnt[rep + g_route[t]], 1);
    __syncthreads();
    if (tid == 0) {
        int off = 0, tl = 0;
        for (int g = 0; g < NOPS; g++) {
            int c = 0;
            for (int rs = 0; rs < 8; rs++) c += cnt[rs * NOPS + g];
            s_cnt[g] = c;
            s_base[g] = off; g_base[g] = off;
            g_cursor[g] = 0;
            s_tb[g] = tl;
            int nt = (c + BM - 1) / BM;
            tl += nt; off += nt * BM;
        }
        s_tb[NOPS] = tl;
        g_ntiles = tl;
    }
    __syncthreads();
    const int ntl = s_tb[NOPS];
    for (int tile = tid; tile < ntl; tile += 256) {
        int g = 0;
        while (tile >= s_tb[g + 1]) g++;
        g_tile_op[tile] = g;
        g_tile_row[tile] = s_base[g] + (tile - s_tb[g]) * BM;
    }
    for (int g = 0; g < NOPS; g++) {
        int c = s_cnt[g];
        int start = s_base[g] + c;
        int end   = s_base[g] + ((c + BM - 1) / BM) * BM;
        for (int p = start + tid; p < end; p += 256) g_perm[p] = -1;
    }
}

// launch 3: scatter token ids into permuted order (perm only; no data movement)
__global__ void scatter_kernel() {
    int t = blockIdx.x * blockDim.x + threadIdx.x;
    if (t >= NTOK) return;
    int op = g_route[t];
    int pos = atomicAdd(&g_cursor[op], 1);
    g_perm[g_base[op] + pos] = t;
}

__device__ __forceinline__ float apply_act(int op, float h) {
    switch (op) {
        case 0:  return 0.5f * h * (1.0f + erff(h * 0.7071067811865476f));
        case 1:  return fmaxf(h, 0.0f);
        case 2:  { float r = fmaxf(h, 0.0f); return r * r; }
        case 3:  return h / (1.0f + expf(-h));
        case 4:  return tanhf(h);
        case 5:  return 1.0f / (1.0f + expf(-h));
        case 6:  return h;
        default: return -h;
    }
}

// ---------------- fp16 MMA grouped GEMM: gathered-A, 3-stage pipeline ----------------
// 256 threads = 8 warps (2 M x 4 N), warp tile 64x32, BK=64 halfs = 128B/row.
// A rows gathered directly from g_Xh via g_perm; padding rows zero-filled by cp.async.
__global__ __launch_bounds__(256, 2)
void gemm_kernel(float* __restrict__ out) {
    extern __shared__ char dsm[];
    const int bx = blockIdx.x;
    if (bx >= g_ntiles) return;

    const int op   = g_tile_op[bx];
    const int row0 = g_tile_row[bx];
    const int n0   = blockIdx.y * BN;
    const int tid  = threadIdx.x;
    const int wid  = tid >> 5;
    const int lid  = tid & 31;
    const int wm   = wid >> 2;     // 0..1
    const int wn   = wid & 3;      // 0..3

    char* sbase = (char*)(((uintptr_t)dsm + 1023) & ~(uintptr_t)1023);
    const uint32_t sb = smem_u32(sbase);

    const __half* __restrict__ Bg0 = g_Wh + (size_t)op * DIM * DIM + (size_t)n0 * DIM;

    // store mapping: 1024 16B units per stage half; r = sid>>3 (row), ks = sid&7
    const int lr = tid >> 3;
    const int ks = tid & 7;
    const uint32_t sw_col = (uint32_t)(ks * 16);

    // gathered A sources: thread covers rows lr + j*32 (j=0..3)
    const __half* asrc[4];
    uint32_t asz[4];
#pragma unroll
    for (int j = 0; j < 4; j++) {
        int tok = g_perm[row0 + lr + j * 32];
        asz[j] = (tok >= 0) ? 16u : 0u;
        int tk = (tok >= 0) ? tok : 0;
        asrc[j] = g_Xh + (size_t)tk * DIM + ks * 8;
    }

    // ldmatrix addressing (validated path: 128B rows, SW128)
    const int a_row = wm * 64 + (lid & 15);
    const uint32_t a_rowoff = (uint32_t)(a_row * 128);
    const uint32_t a_mask = (uint32_t)((a_row & 7) << 4);
    const uint32_t a_col0 = (uint32_t)((lid >> 4) << 4);
    const int b_row = wn * 32 + (lid & 7) + ((lid >> 4) << 3);
    const uint32_t b_rowoff = (uint32_t)(B_OFF + b_row * 128);
    const uint32_t b_mask = (uint32_t)((b_row & 7) << 4);
    const uint32_t b_col0 = (uint32_t)(((lid >> 3) & 1) << 4);

    float acc[4][4][4];
#pragma unroll
    for (int i = 0; i < 4; i++)
#pragma unroll
        for (int j = 0; j < 4; j++)
#pragma unroll
            for (int q = 0; q < 4; q++) acc[i][j][q] = 0.0f;

    auto load_chunk = [&](int kc, int s) {
        const __half* Bg = Bg0 + kc * BK;
        const uint32_t As = sb + s * STAGE_BYTES;
        const uint32_t Bs = As + B_OFF;
#pragma unroll
        for (int j = 0; j < 4; j++) {
            int r = lr + j * 32;
            uint32_t soff = SW128((uint32_t)(r * 128) + sw_col);
            cp_async16z(As + soff, asrc[j] + kc * BK, asz[j]);
            cp_async16(Bs + soff, Bg + (size_t)r * DIM + ks * 8);
        }
        cp_commit();
    };

    load_chunk(0, 0);
    load_chunk(1, 1);

    int s = 0;
    for (int i = 0; i < NITER; i++) {
        cp_wait<1>();
        __syncthreads();
        if (i + 2 < NITER) {
            int s2 = s + 2; if (s2 >= NSTAGE) s2 -= NSTAGE;
            load_chunk(i + 2, s2);
        } else {
            cp_commit();   // keep group count consistent for cp_wait<1>
        }

        const uint32_t stg = sb + s * STAGE_BYTES;
        const uint32_t As_base = stg + a_rowoff;
        const uint32_t Bs_base = stg + b_rowoff;

#pragma unroll
        for (int kk = 0; kk < 4; kk++) {               // 4 x k16 per chunk
            const uint32_t a_col = (a_col0 + kk * 32) ^ a_mask;
            const uint32_t b_col = (b_col0 + kk * 32) ^ b_mask;
            uint32_t a[4][4];
            uint32_t b[4][2];
#pragma unroll
            for (int mi = 0; mi < 4; mi++)
                ldsm_x4(a[mi][0], a[mi][1], a[mi][2], a[mi][3],
                        As_base + mi * (16 * 128) + a_col);
#pragma unroll
            for (int nb = 0; nb < 2; nb++)
                ldsm_x4(b[nb * 2][0], b[nb * 2][1], b[nb * 2 + 1][0], b[nb * 2 + 1][1],
                        Bs_base + nb * (16 * 128) + b_col);
#pragma unroll
            for (int mi = 0; mi < 4; mi++)
#pragma unroll
                for (int ni = 0; ni < 4; ni++)
                    mma_f16(acc[mi][ni], a[mi], b[ni]);
        }

        if (++s >= NSTAGE) s -= NSTAGE;
    }

    // epilogue: activation + scatter to original token rows
    const int r = lid >> 2;
    const int c = (lid & 3) * 2;
#pragma unroll
    for (int mi = 0; mi < 4; mi++) {
        const int m_lo = wm * 64 + mi * 16 + r;
        const int tok_lo = g_perm[row0 + m_lo];
        const int tok_hi = g_perm[row0 + m_lo + 8];
        float* o_lo = (tok_lo >= 0) ? (out + (size_t)tok_lo * DIM + n0) : nullptr;
        float* o_hi = (tok_hi >= 0) ? (out + (size_t)tok_hi * DIM + n0) : nullptr;
#pragma unroll
        for (int ni = 0; ni < 4; ni++) {
            const int n = wn * 32 + ni * 8 + c;
            if (o_lo) {
                float2 v;
                v.x = apply_act(op, acc[mi][ni][0]);
                v.y = apply_act(op, acc[mi][ni][1]);
                *(float2*)(o_lo + n) = v;
            }
            if (o_hi) {
                float2 v;
                v.x = apply_act(op, acc[mi][ni][2]);
                v.y = apply_act(op, acc[mi][ni][3]);
                *(float2*)(o_hi + n) = v;
            }
        }
    }
}

// ---------------- launch ----------------
extern "C" void kernel_launch(void* const* d_in, const int* in_sizes, int n_in,
                              void* d_out, int out_size) {
    const float* x      = (const float*)d_in[0];
    const float* logits = (const float*)d_in[1];
    const float* gumbel = (const float*)d_in[2];
    const float* W      = (const float*)d_in[3];
    float* out          = (float*)d_out;

    cudaFuncSetAttribute(gemm_kernel, cudaFuncAttributeMaxDynamicSharedMemorySize, SMEM_DYN);

    prep_kernel<<<(int)(X_F4 / 256), 256>>>(x, W, logits, gumbel);
    scan_kernel<<<1, 256>>>();
    scatter_kernel<<<(NTOK + 255) / 256, 256>>>();

    dim3 grid(MAX_TILES, DIM / BN);
    gemm_kernel<<<grid, 256, SMEM_DYN>>>(out);
}

// round 17
// speedup vs baseline: 1.1692x; 1.1141x over previous
#include <cuda_runtime.h>
#include <cuda_fp16.h>
#include <math.h>
#include <stdint.h>

// Problem constants
#define NTOK   32768
#define DIM    512
#define NOPS   8

// GEMM tiling: single-pass fp16, BK=64 halfs = 128B/row (SW128 atom)
#define BM 128
#define BN 128
#define BK 64
#define NCHUNK (DIM / BK)      // 8
#define NITER NCHUNK
#define MAX_TILES 264
#define PERM_SIZE (MAX_TILES * BM)

// SMEM: 3 stages x (A 16KB + B 16KB)
#define STAGE_BYTES 32768
#define B_OFF 16384
#define NSTAGE 3
#define SMEM_DYN (NSTAGE * STAGE_BYTES + 1024)

#define SW128(o) ((o) ^ (((o) >> 3) & 0x70))

// ---------------- device scratch ----------------
__device__ int g_route[NTOK];
__device__ int g_cnt[NOPS];       // counted in prep, consumed+rezeroed in scan
__device__ int g_cursor[NOPS];
__device__ int g_base[NOPS];
__device__ int g_perm[PERM_SIZE];
__device__ int g_tile_op[MAX_TILES];
__device__ int g_tile_row[MAX_TILES];
__device__ int g_ntiles;

__device__ __half g_Wh[NOPS * DIM * DIM];        // fp16 W
__device__ __half g_Xh[(size_t)NTOK * DIM];      // fp16 x, ORIGINAL token order

// ---------------- PTX helpers ----------------
__device__ __forceinline__ uint32_t smem_u32(const void* p) {
    uint32_t a;
    asm("{ .reg .u64 t; cvta.to.shared.u64 t, %1; cvt.u32.u64 %0, t; }" : "=r"(a) : "l"(p));
    return a;
}
__device__ __forceinline__ void cp_async16(uint32_t dst, const void* src) {
    asm volatile("cp.async.cg.shared.global [%0], [%1], 16;" :: "r"(dst), "l"(src) : "memory");
}
// zero-fill variant: copies src_size bytes, zero-fills the rest of the 16
__device__ __forceinline__ void cp_async16z(uint32_t dst, const void* src, uint32_t src_size) {
    asm volatile("cp.async.cg.shared.global [%0], [%1], 16, %2;"
                 :: "r"(dst), "l"(src), "r"(src_size) : "memory");
}
__device__ __forceinline__ void cp_commit() {
    asm volatile("cp.async.commit_group;" ::: "memory");
}
template <int N>
__device__ __forceinline__ void cp_wait() {
    asm volatile("cp.async.wait_group %0;" :: "n"(N) : "memory");
}
__device__ __forceinline__ void ldsm_x4(uint32_t& r0, uint32_t& r1, uint32_t& r2, uint32_t& r3,
                                        uint32_t addr) {
    asm volatile("ldmatrix.sync.aligned.m8n8.x4.shared.b16 {%0,%1,%2,%3}, [%4];"
                 : "=r"(r0), "=r"(r1), "=r"(r2), "=r"(r3) : "r"(addr));
}
__device__ __forceinline__ void mma_f16(float* c, const uint32_t* a, const uint32_t* b) {
    asm volatile(
        "mma.sync.aligned.m16n8k16.row.col.f32.f16.f16.f32 "
        "{%0,%1,%2,%3}, {%4,%5,%6,%7}, {%8,%9}, {%0,%1,%2,%3};"
        : "+f"(c[0]), "+f"(c[1]), "+f"(c[2]), "+f"(c[3])
        : "r"(a[0]), "r"(a[1]), "r"(a[2]), "r"(a[3]), "r"(b[0]), "r"(b[1]));
}
__device__ __forceinline__ uint32_t pack_h2(float a, float b) {
    __half2 h = __floats2half2_rn(a, b);
    return *(uint32_t*)&h;
}

// ---------------- aux kernels ----------------

// launch 1: x -> fp16 + W -> fp16 + routing + block-aggregated counting
#define X_F4 ((size_t)NTOK * DIM / 4)        // 4,194,304 float4
#define W_F4 (NOPS * DIM * DIM / 4)          // 524,288 float4
__global__ void prep_kernel(const float* __restrict__ x,
                            const float* __restrict__ W,
                            const float* __restrict__ logits,
                            const float* __restrict__ gumbel) {
    __shared__ int scnt[NOPS];
    const int tid = threadIdx.x;
    size_t i = (size_t)blockIdx.x * blockDim.x + tid;   // 0 .. X_F4-1

    if (tid < NOPS) scnt[tid] = 0;
    __syncthreads();

    float4 v = ((const float4*)x)[i];
    uint2 hv;
    hv.x = pack_h2(v.x, v.y);
    hv.y = pack_h2(v.z, v.w);
    *(uint2*)&g_Xh[i * 4] = hv;

    if (i < W_F4) {
        float4 w = ((const float4*)W)[i];
        uint2 hw;
        hw.x = pack_h2(w.x, w.y);
        hw.y = pack_h2(w.z, w.w);
        *(uint2*)&g_Wh[i * 4] = hw;
    }
    if (i < NTOK) {
        float best = -INFINITY;
        int bi = 0;
#pragma unroll
        for (int k = 0; k < NOPS; k++) {
            float vv = logits[i * NOPS + k] + gumbel[i * NOPS + k];
            if (vv > best) { best = vv; bi = k; }
        }
        g_route[i] = bi;
        atomicAdd(&scnt[bi], 1);
    }
    __syncthreads();
    if (tid < NOPS && scnt[tid] > 0)
        atomicAdd(&g_cnt[tid], scnt[tid]);
}

// launch 2: counts already in g_cnt -> bases + tile metadata + padding; rezero g_cnt
__global__ void scan_kernel() {
    __shared__ int s_base[NOPS], s_tb[NOPS + 1], s_cnt[NOPS];
    const int tid = threadIdx.x;
    if (tid == 0) {
        int off = 0, tl = 0;
        for (int g = 0; g < NOPS; g++) {
            int c = g_cnt[g];
            g_cnt[g] = 0;                 // reset for next graph replay
            s_cnt[g] = c;
            s_base[g] = off; g_base[g] = off;
            g_cursor[g] = 0;
            s_tb[g] = tl;
            int nt = (c + BM - 1) / BM;
            tl += nt; off += nt * BM;
        }
        s_tb[NOPS] = tl;
        g_ntiles = tl;
    }
    __syncthreads();
    const int ntl = s_tb[NOPS];
    for (int tile = tid; tile < ntl; tile += 256) {
        int g = 0;
        while (tile >= s_tb[g + 1]) g++;
        g_tile_op[tile] = g;
        g_tile_row[tile] = s_base[g] + (tile - s_tb[g]) * BM;
    }
    for (int g = 0; g < NOPS; g++) {
        int c = s_cnt[g];
        int start = s_base[g] + c;
        int end   = s_base[g] + ((c + BM - 1) / BM) * BM;
        for (int p = start + tid; p < end; p += 256) g_perm[p] = -1;
    }
}

// launch 3: aggregated scatter — block-local ranks + one global atomic per op per block
__global__ void scatter_kernel() {
    __shared__ int blk_cnt[NOPS];
    __shared__ int blk_base[NOPS];
    const int tid = threadIdx.x;
    const int t = blockIdx.x * 256 + tid;       // NTOK divisible by 256

    if (tid < NOPS) blk_cnt[tid] = 0;
    __syncthreads();
    const int op = g_route[t];
    const int local = atomicAdd(&blk_cnt[op], 1);
    __syncthreads();
    if (tid < NOPS && blk_cnt[tid] > 0)
        blk_base[tid] = atomicAdd(&g_cursor[tid], blk_cnt[tid]);
    __syncthreads();
    g_perm[g_base[op] + blk_base[op] + local] = t;
}

__device__ __forceinline__ float apply_act(int op, float h) {
    switch (op) {
        case 0:  return 0.5f * h * (1.0f + erff(h * 0.7071067811865476f));
        case 1:  return fmaxf(h, 0.0f);
        case 2:  { float r = fmaxf(h, 0.0f); return r * r; }
        case 3:  return h / (1.0f + expf(-h));
        case 4:  return tanhf(h);
        case 5:  return 1.0f / (1.0f + expf(-h));
        case 6:  return h;
        default: return -h;
    }
}

// ---------------- fp16 MMA grouped GEMM: gathered-A, 3-stage pipeline ----------------
// 256 threads = 8 warps (2 M x 4 N), warp tile 64x32, BK=64 halfs = 128B/row.
// A rows gathered directly from g_Xh via g_perm; padding rows zero-filled by cp.async.
__global__ __launch_bounds__(256, 2)
void gemm_kernel(float* __restrict__ out) {
    extern __shared__ char dsm[];
    const int bx = blockIdx.x;
    if (bx >= g_ntiles) return;

    const int op   = g_tile_op[bx];
    const int row0 = g_tile_row[bx];
    const int n0   = blockIdx.y * BN;
    const int tid  = threadIdx.x;
    const int wid  = tid >> 5;
    const int lid  = tid & 31;
    const int wm   = wid >> 2;     // 0..1
    const int wn   = wid & 3;      // 0..3

    char* sbase = (char*)(((uintptr_t)dsm + 1023) & ~(uintptr_t)1023);
    const uint32_t sb = smem_u32(sbase);

    const __half* __restrict__ Bg0 = g_Wh + (size_t)op * DIM * DIM + (size_t)n0 * DIM;

    // store mapping: 1024 16B units per stage half; r = sid>>3 (row), ks = sid&7
    const int lr = tid >> 3;
    const int ks = tid & 7;
    const uint32_t sw_col = (uint32_t)(ks * 16);

    // gathered A sources: thread covers rows lr + j*32 (j=0..3)
    const __half* asrc[4];
    uint32_t asz[4];
#pragma unroll
    for (int j = 0; j < 4; j++) {
        int tok = g_perm[row0 + lr + j * 32];
        asz[j] = (tok >= 0) ? 16u : 0u;
        int tk = (tok >= 0) ? tok : 0;
        asrc[j] = g_Xh + (size_t)tk * DIM + ks * 8;
    }

    // ldmatrix addressing (validated path: 128B rows, SW128)
    const int a_row = wm * 64 + (lid & 15);
    const uint32_t a_rowoff = (uint32_t)(a_row * 128);
    const uint32_t a_mask = (uint32_t)((a_row & 7) << 4);
    const uint32_t a_col0 = (uint32_t)((lid >> 4) << 4);
    const int b_row = wn * 32 + (lid & 7) + ((lid >> 4) << 3);
    const uint32_t b_rowoff = (uint32_t)(B_OFF + b_row * 128);
    const uint32_t b_mask = (uint32_t)((b_row & 7) << 4);
    const uint32_t b_col0 = (uint32_t)(((lid >> 3) & 1) << 4);

    float acc[4][4][4];
#pragma unroll
    for (int i = 0; i < 4; i++)
#pragma unroll
        for (int j = 0; j < 4; j++)
#pragma unroll
            for (int q = 0; q < 4; q++) acc[i][j][q] = 0.0f;

    auto load_chunk = [&](int kc, int s) {
        const __half* Bg = Bg0 + kc * BK;
        const uint32_t As = sb + s * STAGE_BYTES;
        const uint32_t Bs = As + B_OFF;
#pragma unroll
        for (int j = 0; j < 4; j++) {
            int r = lr + j * 32;
            uint32_t soff = SW128((uint32_t)(r * 128) + sw_col);
            cp_async16z(As + soff, asrc[j] + kc * BK, asz[j]);
            cp_async16(Bs + soff, Bg + (size_t)r * DIM + ks * 8);
        }
        cp_commit();
    };

    load_chunk(0, 0);
    load_chunk(1, 1);

    int s = 0;
    for (int i = 0; i < NITER; i++) {
        cp_wait<1>();
        __syncthreads();
        if (i + 2 < NITER) {
            int s2 = s + 2; if (s2 >= NSTAGE) s2 -= NSTAGE;
            load_chunk(i + 2, s2);
        } else {
            cp_commit();   // keep group count consistent for cp_wait<1>
        }

        const uint32_t stg = sb + s * STAGE_BYTES;
        const uint32_t As_base = stg + a_rowoff;
        const uint32_t Bs_base = stg + b_rowoff;

#pragma unroll
        for (int kk = 0; kk < 4; kk++) {               // 4 x k16 per chunk
            const uint32_t a_col = (a_col0 + kk * 32) ^ a_mask;
            const uint32_t b_col = (b_col0 + kk * 32) ^ b_mask;
            uint32_t a[4][4];
            uint32_t b[4][2];
#pragma unroll
            for (int mi = 0; mi < 4; mi++)
                ldsm_x4(a[mi][0], a[mi][1], a[mi][2], a[mi][3],
                        As_base + mi * (16 * 128) + a_col);
#pragma unroll
            for (int nb = 0; nb < 2; nb++)
                ldsm_x4(b[nb * 2][0], b[nb * 2][1], b[nb * 2 + 1][0], b[nb * 2 + 1][1],
                        Bs_base + nb * (16 * 128) + b_col);
#pragma unroll
            for (int mi = 0; mi < 4; mi++)
#pragma unroll
                for (int ni = 0; ni < 4; ni++)
                    mma_f16(acc[mi][ni], a[mi], b[ni]);
        }

        if (++s >= NSTAGE) s -= NSTAGE;
    }

    // epilogue: activation + scatter to original token rows
    const int r = lid >> 2;
    const int c = (lid & 3) * 2;
#pragma unroll
    for (int mi = 0; mi < 4; mi++) {
        const int m_lo = wm * 64 + mi * 16 + r;
        const int tok_lo = g_perm[row0 + m_lo];
        const int tok_hi = g_perm[row0 + m_lo + 8];
        float* o_lo = (tok_lo >= 0) ? (out + (size_t)tok_lo * DIM + n0) : nullptr;
        float* o_hi = (tok_hi >= 0) ? (out + (size_t)tok_hi * DIM + n0) : nullptr;
#pragma unroll
        for (int ni = 0; ni < 4; ni++) {
            const int n = wn * 32 + ni * 8 + c;
            if (o_lo) {
                float2 v;
                v.x = apply_act(op, acc[mi][ni][0]);
                v.y = apply_act(op, acc[mi][ni][1]);
                *(float2*)(o_lo + n) = v;
            }
            if (o_hi) {
                float2 v;
                v.x = apply_act(op, acc[mi][ni][2]);
                v.y = apply_act(op, acc[mi][ni][3]);
                *(float2*)(o_hi + n) = v;
            }
        }
    }
}

// ---------------- launch ----------------
extern "C" void kernel_launch(void* const* d_in, const int* in_sizes, int n_in,
                              void* d_out, int out_size) {
    const float* x      = (const float*)d_in[0];
    const float* logits = (const float*)d_in[1];
    const float* gumbel = (const float*)d_in[2];
    const float* W      = (const float*)d_in[3];
    float* out          = (float*)d_out;

    cudaFuncSetAttribute(gemm_kernel, cudaFuncAttributeMaxDynamicSharedMemorySize, SMEM_DYN);

    prep_kernel<<<(int)(X_F4 / 256), 256>>>(x, W, logits, gumbel);
    scan_kernel<<<1, 256>>>();
    scatter_kernel<<<NTOK / 256, 256>>>();

    dim3 grid(MAX_TILES, DIM / BN);
    gemm_kernel<<<grid, 256, SMEM_DYN>>>(out);
}